// round 2
// baseline (speedup 1.0000x reference)
#include <cuda_runtime.h>

// ---------------- problem constants ----------------
#define CIN    2312
#define HID    300
#define NOUT   10
#define BATCH  128
#define T0     50
#define PAD    5
#define TP1    55          // T0 + PAD
#define T1     51          // conv1 output length
#define HP     56          // T1 + PAD
#define T2     52          // conv2 output length
#define KS     5
#define K1TOT  (KS*CIN)    // 11560
#define K2TOT  (KS*HID)    // 1500
#define M1     (BATCH*T1)  // 6528
#define M2     (BATCH*T2)  // 6656
#define BETA   0.9f
#define THRESH 1.0f

// ---------------- scratch (device globals; no allocation allowed) ----------------
__device__ float g_Xpad[BATCH*TP1*CIN];   // [B][55][CIN]
__device__ float g_B1[K1TOT*HID];         // [kk=(dt*CIN+i)][o]
__device__ float g_Y1[M1*HID];            // [b*T1+t][HID]
__device__ float g_Hpad[BATCH*HP*HID];    // [B][56][HID]  spikes, left-padded
__device__ float g_B2t[NOUT*K2TOT];       // [o][kk=(dt*HID+h)]
__device__ float g_Y2[M2*NOUT];           // [b*T2+t][NOUT]

// ---------------- prep: pad + copy input ----------------
__global__ void prep_x(const float* __restrict__ data) {
    const int C4 = CIN / 4;                 // 578
    const int PER_B = TP1 * C4;             // 31790
    int v = blockIdx.x * blockDim.x + threadIdx.x;
    if (v >= BATCH * PER_B) return;
    int b = v / PER_B;
    int r = v - b * PER_B;
    int t = r / C4;
    int i4 = r - t * C4;
    float4 val = make_float4(0.f, 0.f, 0.f, 0.f);
    if (t >= PAD) {
        val = reinterpret_cast<const float4*>(data)[(b * T0 + (t - PAD)) * C4 + i4];
    }
    reinterpret_cast<float4*>(g_Xpad)[v] = val;
}

// ---------------- DCLS gaussian kernel synthesis (fp32, mimicking reference ops) ----------------
__device__ __forceinline__ void gauss5(float p, float g[KS]) {
    float c = p + 2.0f;                     // MAX_DELAY // 2
    float s = 0.f;
#pragma unroll
    for (int k = 0; k < KS; k++) {
        float d = ((float)k - c) * 0.5f;    // (idx - c)/SIG, SIG=2 (exact binary scale)
        g[k] = expf(-0.5f * (d * d));
        s += g[k];                          // sequential sum, same order as jnp
    }
    float den = s + 1e-7f;
#pragma unroll
    for (int k = 0; k < KS; k++) g[k] = g[k] / den;
}

__global__ void make_B1(const float* __restrict__ W1, const float* __restrict__ P1) {
    int tid = blockIdx.x * blockDim.x + threadIdx.x;
    if (tid >= CIN * HID) return;
    int i = tid / HID;
    int o = tid - i * HID;
    float w = W1[o * CIN + i];
    float p = P1[o * CIN + i];
    float g[KS];
    gauss5(p, g);
#pragma unroll
    for (int k = 0; k < KS; k++) {
        g_B1[(size_t)(k * CIN + i) * HID + o] = w * g[k];
    }
}

__global__ void make_B2(const float* __restrict__ W2, const float* __restrict__ P2) {
    int tid = blockIdx.x * blockDim.x + threadIdx.x;
    if (tid >= HID * NOUT) return;
    int h = tid / NOUT;
    int o = tid - h * NOUT;
    float w = W2[o * HID + h];
    float p = P2[o * HID + h];
    float g[KS];
    gauss5(p, g);
#pragma unroll
    for (int k = 0; k < KS; k++) {
        g_B2t[o * K2TOT + k * HID + h] = w * g[k];
    }
}

// ---------------- GEMM1 with two-level (blocked) accumulation ----------------
// Y1[m, o] = sum_kk A[m, kk] * B1[kk, o] + b1[o]
// BM=128, BN=64, BK=8, 256 threads, 8x4 micro-tile.
// Low accumulators flushed into high accumulators every 32 BK-tiles (256 k terms)
// => reduction rounding error ~1.9e-7 abs instead of ~2.3e-6 (sequential).
__global__ void __launch_bounds__(256) gemm1(const float* __restrict__ b1) {
    __shared__ float As[8][128];
    __shared__ float Bs[8][64];

    const int n0 = blockIdx.x * 64;
    const int m0 = blockIdx.y * 128;
    const int tid = threadIdx.x;

    const int ar = tid >> 1;                 // 0..127 row within tile
    const int ac4 = (tid & 1) * 4;           // 0 or 4
    const int m = m0 + ar;
    const int bb = m / T1;
    const int tt = m - bb * T1;
    const float* Arow = g_Xpad + (size_t)(bb * TP1 + tt) * CIN;

    const int bkr = tid >> 4;
    const int bnc = (tid & 15) * 4;
    const bool bload = (tid < 128) && (n0 + bnc + 3 < HID);

    const int tr = tid >> 4;                 // rows tr*8..tr*8+7
    const int tc = tid & 15;                 // cols tc*4..tc*4+3

    float accL[8][4], accH[8][4];
#pragma unroll
    for (int i = 0; i < 8; i++)
#pragma unroll
        for (int j = 0; j < 4; j++) { accL[i][j] = 0.f; accH[i][j] = 0.f; }

    int it = 0;
    for (int k0 = 0; k0 < K1TOT; k0 += 8, it++) {
        float4 av = *reinterpret_cast<const float4*>(Arow + k0 + ac4);
        float4 bv = make_float4(0.f, 0.f, 0.f, 0.f);
        if (bload) bv = *reinterpret_cast<const float4*>(g_B1 + (size_t)(k0 + bkr) * HID + n0 + bnc);

        __syncthreads();
        As[ac4 + 0][ar] = av.x;
        As[ac4 + 1][ar] = av.y;
        As[ac4 + 2][ar] = av.z;
        As[ac4 + 3][ar] = av.w;
        if (tid < 128) *reinterpret_cast<float4*>(&Bs[bkr][bnc]) = bv;
        __syncthreads();

#pragma unroll
        for (int kk = 0; kk < 8; kk++) {
            float a[8];
#pragma unroll
            for (int i = 0; i < 8; i++) a[i] = As[kk][tr * 8 + i];
            float4 bq = *reinterpret_cast<const float4*>(&Bs[kk][tc * 4]);
#pragma unroll
            for (int i = 0; i < 8; i++) {
                accL[i][0] = __fmaf_rn(a[i], bq.x, accL[i][0]);
                accL[i][1] = __fmaf_rn(a[i], bq.y, accL[i][1]);
                accL[i][2] = __fmaf_rn(a[i], bq.z, accL[i][2]);
                accL[i][3] = __fmaf_rn(a[i], bq.w, accL[i][3]);
            }
        }

        if ((it & 31) == 31) {   // flush low -> high every 256 k terms
#pragma unroll
            for (int i = 0; i < 8; i++)
#pragma unroll
                for (int j = 0; j < 4; j++) { accH[i][j] += accL[i][j]; accL[i][j] = 0.f; }
        }
    }
    // final flush
#pragma unroll
    for (int i = 0; i < 8; i++)
#pragma unroll
        for (int j = 0; j < 4; j++) accH[i][j] += accL[i][j];

    // epilogue: add bias, store
#pragma unroll
    for (int i = 0; i < 8; i++) {
        int mm = m0 + tr * 8 + i;
        size_t row = (size_t)mm * HID;
#pragma unroll
        for (int j = 0; j < 4; j++) {
            int n = n0 + tc * 4 + j;
            if (n < HID) g_Y1[row + n] = accH[i][j] + b1[n];
        }
    }
}

// ---------------- LIF layer 1 ----------------
__global__ void lif1() {
    int tid = blockIdx.x * blockDim.x + threadIdx.x;
    if (tid >= BATCH * HID) return;
    int b = tid / HID;
    int h = tid - b * HID;
#pragma unroll
    for (int tp = 0; tp < PAD; tp++)
        g_Hpad[(size_t)(b * HP + tp) * HID + h] = 0.f;
    float mem = 0.f;
    for (int t = 0; t < T1; t++) {
        float x = g_Y1[(size_t)(b * T1 + t) * HID + h];
        float reset = (mem > THRESH) ? 1.f : 0.f;
        // (BETA*mem + x) - reset*THRESH, fma-contracted like XLA
        mem = __fmaf_rn(BETA, mem, x) - reset * THRESH;
        float spk = (mem > THRESH) ? 1.f : 0.f;
        g_Hpad[(size_t)(b * HP + PAD + t) * HID + h] = spk;
    }
}

// ---------------- GEMM2: one warp per output row ----------------
__global__ void gemm2(const float* __restrict__ b2) {
    int gw = (blockIdx.x * blockDim.x + threadIdx.x) >> 5;
    int lane = threadIdx.x & 31;
    if (gw >= M2) return;
    int b = gw / T2;
    int t = gw - b * T2;
    const float* Arow = g_Hpad + (size_t)(b * HP + t) * HID;

    float acc[NOUT];
#pragma unroll
    for (int o = 0; o < NOUT; o++) acc[o] = 0.f;

    for (int kk = lane; kk < K2TOT; kk += 32) {
        float x = Arow[kk];
#pragma unroll
        for (int o = 0; o < NOUT; o++)
            acc[o] = __fmaf_rn(x, g_B2t[o * K2TOT + kk], acc[o]);
    }
#pragma unroll
    for (int o = 0; o < NOUT; o++) {
#pragma unroll
        for (int off = 16; off > 0; off >>= 1)
            acc[o] += __shfl_down_sync(0xffffffffu, acc[o], off);
    }
    if (lane == 0) {
#pragma unroll
        for (int o = 0; o < NOUT; o++)
            g_Y2[(size_t)gw * NOUT + o] = acc[o] + b2[o];
    }
}

// ---------------- LIF layer 2: spk2 and mem2 straight to d_out ----------------
__global__ void lif2(float* __restrict__ out) {
    int tid = blockIdx.x * blockDim.x + threadIdx.x;
    if (tid >= BATCH * NOUT) return;
    int b = tid / NOUT;
    int o = tid - b * NOUT;
    const int HALF = T2 * BATCH * NOUT;     // 66560
    float mem = 0.f;
    for (int t = 0; t < T2; t++) {
        float x = g_Y2[(size_t)(b * T2 + t) * NOUT + o];
        float reset = (mem > THRESH) ? 1.f : 0.f;
        mem = __fmaf_rn(BETA, mem, x) - reset * THRESH;
        float spk = (mem > THRESH) ? 1.f : 0.f;
        int idx = (t * BATCH + b) * NOUT + o;
        out[idx] = spk;
        out[HALF + idx] = mem;
    }
}

// ---------------- launch ----------------
extern "C" void kernel_launch(void* const* d_in, const int* in_sizes, int n_in,
                              void* d_out, int out_size) {
    const float* data = (const float*)d_in[0];
    const float* W1   = (const float*)d_in[1];
    const float* P1   = (const float*)d_in[2];
    const float* b1   = (const float*)d_in[3];
    const float* W2   = (const float*)d_in[4];
    const float* P2   = (const float*)d_in[5];
    const float* b2   = (const float*)d_in[6];
    float* out = (float*)d_out;

    {
        int n4 = BATCH * TP1 * (CIN / 4);
        prep_x<<<(n4 + 255) / 256, 256>>>(data);
    }
    make_B1<<<(CIN * HID + 255) / 256, 256>>>(W1, P1);
    make_B2<<<(HID * NOUT + 255) / 256, 256>>>(W2, P2);

    {
        dim3 grid(5, 51);
        gemm1<<<grid, 256>>>(b1);
    }
    lif1<<<(BATCH * HID + 255) / 256, 256>>>();

    {
        int blocks = (M2 * 32 + 255) / 256;
        gemm2<<<blocks, 256>>>(b2);
    }
    lif2<<<(BATCH * NOUT + 255) / 256, 256>>>(out);
}